// round 5
// baseline (speedup 1.0000x reference)
#include <cuda_runtime.h>
#include <stdint.h>

#define FULL 0xffffffffu

constexpr int Bb = 8;
constexpr int Nn = 16384;
constexpr int Gg = 257;
constexpr int Kk = 32;
constexpr float MARGIN = 1e-3f;   // >> 8e-5 worst-case |exact-approx| bound

// Sphere-grid centers (filled by init kernel each launch; deterministic).
__device__ float g_cx[Gg];
__device__ float g_cy[Gg];
__device__ float g_cz[Gg];

__global__ void init_centers_kernel() {
    __shared__ int pf[736];
    int t = threadIdx.x;            // 736 threads
    int keep = 0;
    float x = 0.f, y = 0.f, z = 0.f;
    if (t < 729) {
        int i = t / 81, j = (t / 9) % 9, k = t % 9;
        x = 0.25f * (float)i - 1.0f;
        y = 0.25f * (float)j - 1.0f;
        z = 0.25f * (float)k - 1.0f;
        float n2 = x * x + y * y + z * z;
        keep = (n2 <= 1.00001f) ? 1 : 0;
    }
    pf[t] = keep;
    __syncthreads();
    for (int s = 1; s < 736; s <<= 1) {
        int v = (t >= s) ? pf[t - s] : 0;
        __syncthreads();
        pf[t] += v;
        __syncthreads();
    }
    if (keep) {
        int p = pf[t] - 1;
        g_cx[p] = x; g_cy[p] = y; g_cz[p] = z;
    }
}

__device__ __forceinline__ unsigned long long ull_min(unsigned long long a,
                                                      unsigned long long b) {
    return a < b ? a : b;
}
__device__ __forceinline__ unsigned long long ull_max(unsigned long long a,
                                                      unsigned long long b) {
    return a < b ? b : a;
}

// 1024 threads: 2 warps per center (each scans half the cloud), SoA smem,
// float4 LDS, cheap conservative filter, exact slow path, bitonic pair-merge.
__global__ __launch_bounds__(1024, 1)
void knn_group_kernel(const float* __restrict__ xyz,
                      const float* __restrict__ labels,
                      const float* __restrict__ inside,
                      float* __restrict__ out) {
    extern __shared__ float s[];                 // sx|sy|sz (+ merge buf)
    float* sx = s;
    float* sy = s + Nn;
    float* sz = s + 2 * Nn;
    unsigned long long* smerge =
        reinterpret_cast<unsigned long long*>(s + 3 * Nn);   // 32 warps * 32

    const int b = blockIdx.y;
    const int tid = threadIdx.x;

    // AoS global -> SoA shared (float4 coalesced loads, scalar stores).
    {
        const float4* src = reinterpret_cast<const float4*>(xyz + (size_t)b * Nn * 3);
        for (int i = tid; i < Nn * 3 / 4; i += blockDim.x) {
            const float4 v = src[i];
            const int e = 4 * i;
            s[(e % 3) * Nn + e / 3]             = v.x;
            s[((e + 1) % 3) * Nn + (e + 1) / 3] = v.y;
            s[((e + 2) % 3) * Nn + (e + 2) / 3] = v.z;
            s[((e + 3) % 3) * Nn + (e + 3) / 3] = v.w;
        }
    }
    __syncthreads();

    const int wid    = tid >> 5;      // 0..31
    const int lane   = tid & 31;
    const int gi     = wid >> 1;      // center slot 0..15
    const int parity = wid & 1;       // which half of the cloud
    const int g      = blockIdx.x * 16 + gi;
    const bool active = (g < Gg);

    unsigned long long key = ~0ull;   // lane r = rank-r key, ascending
    float cx = 0.f, cy = 0.f, cz = 0.f;

    if (active) {
        cx = g_cx[g]; cy = g_cy[g]; cz = g_cz[g];
        const float c2 = cx * cx + cy * cy + cz * cz;   // exact lattice arith

        unsigned long long thresh = ~0ull;
        float thresh_f = __int_as_float(0x7f800000);    // +inf

        const float4* sx4 = reinterpret_cast<const float4*>(sx);
        const float4* sy4 = reinterpret_cast<const float4*>(sy);
        const float4* sz4 = reinterpret_cast<const float4*>(sz);
        const int half = parity * (Nn / 8);             // float4 units: 2048

        for (int it = 0; it < 32; ++it) {               // 256 pts/warp/round
            const int j0 = half + it * 64 + lane;
            const int j1 = j0 + 32;
            const float4 xa = sx4[j0], xb = sx4[j1];
            const float4 ya = sy4[j0], yb = sy4[j1];
            const float4 za = sz4[j0], zb = sz4[j1];

            const float xs[8] = {xa.x, xa.y, xa.z, xa.w, xb.x, xb.y, xb.z, xb.w};
            const float ys[8] = {ya.x, ya.y, ya.z, ya.w, yb.x, yb.y, yb.z, yb.w};
            const float zs[8] = {za.x, za.y, za.z, za.w, zb.x, zb.y, zb.z, zb.w};

            // Cheap conservative filter (approx distance, inflated threshold).
            const float tplus = thresh_f + MARGIN;      // NaN while unfilled
            bool hit = false;
            #pragma unroll
            for (int u = 0; u < 8; ++u) {
                const float dx = xs[u] - cx;
                const float dy = ys[u] - cy;
                const float dz = zs[u] - cz;
                const float da = __fmaf_rn(dz, dz, __fmaf_rn(dy, dy, dx * dx));
                hit |= !(da > tplus);                   // NaN-safe, tie-safe
            }

            if (__ballot_sync(FULL, hit)) {
                // Exact slow path. FROZEN precision model (rel_err==0):
                //   x2 = fma(z,z, fma(y,y, rn(x*x)))
                //   dt = fma(cz,z, fma(cy,y, rn(cx*x)))
                //   d2 = (c2 + x2) - 2*dt
                #pragma unroll
                for (int u = 0; u < 8; ++u) {
                    const float x = xs[u], y = ys[u], z = zs[u];
                    const float x2 = __fmaf_rn(z, z,
                                     __fmaf_rn(y, y, __fmul_rn(x, x)));
                    const float dt = __fmaf_rn(cz, z,
                                     __fmaf_rn(cy, y, __fmul_rn(cx, x)));
                    const float d2 = __fsub_rn(__fadd_rn(c2, x2),
                                               __fmul_rn(2.0f, dt));
                    const int p = (u < 4) ? (4 * j0 + u) : (4 * j1 + u - 4);

                    unsigned uu = __float_as_uint(d2);
                    uu = (uu & 0x80000000u) ? ~uu : (uu | 0x80000000u);
                    const unsigned long long nk =
                        ((unsigned long long)uu << 32) | (unsigned)p;

                    unsigned m = __ballot_sync(FULL, nk < thresh);
                    while (m) {
                        const int srcl = __ffs(m) - 1;
                        m &= m - 1;
                        const unsigned long long cand = __shfl_sync(FULL, nk, srcl);
                        if (cand >= thresh) continue;
                        const int pos = __popc(__ballot_sync(FULL, key < cand));
                        const unsigned long long up = __shfl_up_sync(FULL, key, 1);
                        if (lane > pos)       key = up;
                        else if (lane == pos) key = cand;
                        thresh = __shfl_sync(FULL, key, 31);
                    }
                }
                const unsigned tu = (unsigned)(thresh >> 32);
                const unsigned ob = (tu & 0x80000000u) ? (tu ^ 0x80000000u) : ~tu;
                thresh_f = __uint_as_float(ob);         // NaN until filled
            }
        }
    }

    // Pair-merge: warps (2i, 2i+1) hold sorted top-32 of disjoint halves.
    if (active) smerge[wid * 32 + lane] = key;
    __syncthreads();

    if (active && parity == 0) {
        // min(A[r], B[31-r]) = lowest-32 of the union, bitonic; then sort.
        unsigned long long mk = ull_min(key, smerge[(wid + 1) * 32 + (31 - lane)]);
        #pragma unroll
        for (int d = 16; d >= 1; d >>= 1) {
            const unsigned long long o = __shfl_xor_sync(FULL, mk, d);
            mk = (lane & d) ? ull_max(mk, o) : ull_min(mk, o);
        }

        const int idx = (int)(mk & 0xffffffffu);
        const float px = sx[idx];
        const float py = sy[idx];
        const float pz = sz[idx];
        const int bg = b * Gg + g;

        float* o0 = out;                                   // neigh [B,G,32,3]
        float* o1 = o0 + (size_t)Bb * Gg * Kk * 3;         // center [B,G,3]
        float* o2 = o1 + (size_t)Bb * Gg * 3;              // labels [B,G,32,1]
        float* o3 = o2 + (size_t)Bb * Gg * Kk;             // idx    [B,G,32]
        float* o4 = o3 + (size_t)Bb * Gg * Kk;             // inside [B,G,32,1]

        const int r0 = (bg * Kk + lane) * 3;
        o0[r0 + 0] = __fsub_rn(px, cx);
        o0[r0 + 1] = __fsub_rn(py, cy);
        o0[r0 + 2] = __fsub_rn(pz, cz);
        if (lane == 0) {
            o1[bg * 3 + 0] = cx;
            o1[bg * 3 + 1] = cy;
            o1[bg * 3 + 2] = cz;
        }
        o2[bg * Kk + lane] = labels[b * Nn + idx];
        o3[bg * Kk + lane] = (float)idx;
        o4[bg * Kk + lane] = inside[b * Nn + idx];
    }
}

extern "C" void kernel_launch(void* const* d_in, const int* in_sizes, int n_in,
                              void* d_out, int out_size) {
    const float* xyz    = (const float*)d_in[0];
    const float* labels = (const float*)d_in[1];
    const float* inside = (const float*)d_in[2];
    float* out = (float*)d_out;

    (void)in_sizes; (void)n_in; (void)out_size;

    init_centers_kernel<<<1, 736>>>();

    const int smem = Nn * 3 * sizeof(float) + 32 * 32 * sizeof(unsigned long long);
    cudaFuncSetAttribute(knn_group_kernel,
                         cudaFuncAttributeMaxDynamicSharedMemorySize, smem);
    dim3 grid((Gg + 15) / 16, Bb);
    knn_group_kernel<<<grid, 1024, smem>>>(xyz, labels, inside, out);
}

// round 6
// speedup vs baseline: 1.1127x; 1.1127x over previous
#include <cuda_runtime.h>
#include <stdint.h>

#define FULL 0xffffffffu

constexpr int Bb = 8;
constexpr int Nn = 16384;
constexpr int Gg = 257;
constexpr int Kk = 32;

// Sphere-grid centers (filled by init kernel each launch; deterministic).
__device__ float g_cx[Gg];
__device__ float g_cy[Gg];
__device__ float g_cz[Gg];

__global__ void init_centers_kernel() {
    __shared__ int pf[736];
    int t = threadIdx.x;            // 736 threads
    int keep = 0;
    float x = 0.f, y = 0.f, z = 0.f;
    if (t < 729) {
        int i = t / 81, j = (t / 9) % 9, k = t % 9;
        x = 0.25f * (float)i - 1.0f;
        y = 0.25f * (float)j - 1.0f;
        z = 0.25f * (float)k - 1.0f;
        float n2 = x * x + y * y + z * z;
        keep = (n2 <= 1.00001f) ? 1 : 0;
    }
    pf[t] = keep;
    __syncthreads();
    for (int s = 1; s < 736; s <<= 1) {
        int v = (t >= s) ? pf[t - s] : 0;
        __syncthreads();
        pf[t] += v;
        __syncthreads();
    }
    if (keep) {
        int p = pf[t] - 1;
        g_cx[p] = x; g_cy[p] = y; g_cz[p] = z;
    }
}

// ---- packed f32x2 exact helpers (two independent IEEE-rn fp32 lanes) ----
__device__ __forceinline__ uint64_t f2fma(uint64_t a, uint64_t b, uint64_t c) {
    uint64_t d; asm("fma.rn.f32x2 %0, %1, %2, %3;" : "=l"(d) : "l"(a), "l"(b), "l"(c));
    return d;
}
__device__ __forceinline__ uint64_t f2mul(uint64_t a, uint64_t b) {
    uint64_t d; asm("mul.rn.f32x2 %0, %1, %2;" : "=l"(d) : "l"(a), "l"(b));
    return d;
}
__device__ __forceinline__ uint64_t f2add(uint64_t a, uint64_t b) {
    uint64_t d; asm("add.rn.f32x2 %0, %1, %2;" : "=l"(d) : "l"(a), "l"(b));
    return d;
}
__device__ __forceinline__ uint64_t f2pack(float lo, float hi) {
    uint64_t d; asm("mov.b64 %0, {%1, %2};" : "=l"(d) : "f"(lo), "f"(hi));
    return d;
}
__device__ __forceinline__ void f2unpack(uint64_t v, float& lo, float& hi) {
    asm("mov.b64 {%0, %1}, %2;" : "=f"(lo), "=f"(hi) : "l"(v));
}

__device__ __forceinline__ unsigned long long ull_min(unsigned long long a,
                                                      unsigned long long b) {
    return a < b ? a : b;
}
__device__ __forceinline__ unsigned long long ull_max(unsigned long long a,
                                                      unsigned long long b) {
    return a < b ? b : a;
}

// 1024 threads: 2 warps per center, each scans half the cloud (SoA smem,
// LDS.128 as 2x f32x2). Exact packed d2 in fast path, FMNMX-tree filter,
// REDUX-gated slow path, bitonic pair-merge at the end.
__global__ __launch_bounds__(1024, 1)
void knn_group_kernel(const float* __restrict__ xyz,
                      const float* __restrict__ labels,
                      const float* __restrict__ inside,
                      float* __restrict__ out) {
    extern __shared__ float s[];                 // sx|sy|sz (+ merge buf)
    float* sx = s;
    float* sy = s + Nn;
    float* sz = s + 2 * Nn;
    unsigned long long* smerge =
        reinterpret_cast<unsigned long long*>(s + 3 * Nn);   // 32 warps * 32

    const int b = blockIdx.y;
    const int tid = threadIdx.x;

    // AoS global -> SoA shared (float4 coalesced loads, scalar stores).
    {
        const float4* src = reinterpret_cast<const float4*>(xyz + (size_t)b * Nn * 3);
        for (int i = tid; i < Nn * 3 / 4; i += blockDim.x) {
            const float4 v = src[i];
            const int e = 4 * i;
            s[(e % 3) * Nn + e / 3]             = v.x;
            s[((e + 1) % 3) * Nn + (e + 1) / 3] = v.y;
            s[((e + 2) % 3) * Nn + (e + 2) / 3] = v.z;
            s[((e + 3) % 3) * Nn + (e + 3) / 3] = v.w;
        }
    }
    __syncthreads();

    const int wid    = tid >> 5;      // 0..31
    const int lane   = tid & 31;
    const int gi     = wid >> 1;      // center slot 0..15
    const int parity = wid & 1;       // which half of the cloud
    const int g      = blockIdx.x * 16 + gi;
    const bool active = (g < Gg);

    unsigned long long key = ~0ull;   // lane r = rank-r key, ascending
    float cx = 0.f, cy = 0.f, cz = 0.f;

    if (active) {
        cx = g_cx[g]; cy = g_cy[g]; cz = g_cz[g];
        const float c2 = cx * cx + cy * cy + cz * cz;   // exact lattice arith

        const uint64_t cx2 = f2pack(cx, cx);
        const uint64_t cy2 = f2pack(cy, cy);
        const uint64_t cz2 = f2pack(cz, cz);
        const uint64_t c22 = f2pack(c2, c2);
        const uint64_t n22 = f2pack(-2.0f, -2.0f);

        unsigned long long thresh = ~0ull;
        float thresh_f = __int_as_float(0x7f800000);    // +inf

        // FROZEN precision model per fp32 lane (verified rel_err == 0):
        //   x2 = fma(z,z, fma(y,y, rn(x*x)))
        //   dt = fma(cz,z, fma(cy,y, rn(cx*x)))
        //   d2 = (c2 + x2) + rn(-2*dt)        [== (c2+x2) - rn(2*dt) exactly]
        auto d2pair = [&](uint64_t xp, uint64_t yp, uint64_t zp) -> uint64_t {
            const uint64_t x2 = f2fma(zp, zp, f2fma(yp, yp, f2mul(xp, xp)));
            const uint64_t dt = f2fma(cz2, zp, f2fma(cy2, yp, f2mul(cx2, xp)));
            return f2add(f2add(c22, x2), f2mul(dt, n22));
        };

        // Exact 64-bit key insertion into the sorted-per-lane top-32.
        auto insert = [&](float d2v, int p) {
            unsigned uu = __float_as_uint(d2v);
            uu = (uu & 0x80000000u) ? ~uu : (uu | 0x80000000u);
            const unsigned long long nk =
                ((unsigned long long)uu << 32) | (unsigned)p;
            unsigned m = __ballot_sync(FULL, nk < thresh);
            while (m) {
                const int srcl = __ffs(m) - 1;
                m &= m - 1;
                const unsigned long long cand = __shfl_sync(FULL, nk, srcl);
                if (cand >= thresh) continue;
                const int pos = __popc(__ballot_sync(FULL, key < cand));
                const unsigned long long up = __shfl_up_sync(FULL, key, 1);
                if (lane > pos)       key = up;
                else if (lane == pos) key = cand;
                thresh = __shfl_sync(FULL, key, 31);
            }
        };

        const int half = parity * 2048;              // float4 units per half

        for (int it = 0; it < 32; ++it) {            // 256 pts/warp/round
            const int j0 = half + it * 64 + lane;
            const int j1 = j0 + 32;

            // Each LDS.128 yields two packed f32x2 point-pairs.
            const ulonglong2 xa = *reinterpret_cast<const ulonglong2*>(sx + 4 * j0);
            const ulonglong2 ya = *reinterpret_cast<const ulonglong2*>(sy + 4 * j0);
            const ulonglong2 za = *reinterpret_cast<const ulonglong2*>(sz + 4 * j0);
            const ulonglong2 xb = *reinterpret_cast<const ulonglong2*>(sx + 4 * j1);
            const ulonglong2 yb = *reinterpret_cast<const ulonglong2*>(sy + 4 * j1);
            const ulonglong2 zb = *reinterpret_cast<const ulonglong2*>(sz + 4 * j1);

            const uint64_t dA = d2pair(xa.x, ya.x, za.x);   // pts 4j0+0,1
            const uint64_t dB = d2pair(xa.y, ya.y, za.y);   // pts 4j0+2,3
            const uint64_t dC = d2pair(xb.x, yb.x, zb.x);   // pts 4j1+0,1
            const uint64_t dD = d2pair(xb.y, yb.y, zb.y);   // pts 4j1+2,3

            float d0, d1, d2_, d3, d4, d5, d6, d7;
            f2unpack(dA, d0, d1);
            f2unpack(dB, d2_, d3);
            f2unpack(dC, d4, d5);
            f2unpack(dD, d6, d7);

            // FMNMX min-tree -> single trigger compare (exact, no margin).
            const float m01 = fminf(d0, d1), m23 = fminf(d2_, d3);
            const float m45 = fminf(d4, d5), m67 = fminf(d6, d7);
            const float mlo = fminf(m01, m23), mhi = fminf(m45, m67);
            const float min8 = fminf(mlo, mhi);

            if (__ballot_sync(FULL, min8 <= thresh_f)) {
                // Per-point hit bits (superset; thresh only tightens later).
                unsigned bits = 0;
                bits |= (d0  <= thresh_f) ? 0x01u : 0u;
                bits |= (d1  <= thresh_f) ? 0x02u : 0u;
                bits |= (d2_ <= thresh_f) ? 0x04u : 0u;
                bits |= (d3  <= thresh_f) ? 0x08u : 0u;
                bits |= (d4  <= thresh_f) ? 0x10u : 0u;
                bits |= (d5  <= thresh_f) ? 0x20u : 0u;
                bits |= (d6  <= thresh_f) ? 0x40u : 0u;
                bits |= (d7  <= thresh_f) ? 0x80u : 0u;
                const unsigned am = __reduce_or_sync(FULL, bits);  // warp-uniform

                const int p0 = 4 * j0, p1 = 4 * j1;
                if (am & 0x01u) insert(d0,  p0 + 0);
                if (am & 0x02u) insert(d1,  p0 + 1);
                if (am & 0x04u) insert(d2_, p0 + 2);
                if (am & 0x08u) insert(d3,  p0 + 3);
                if (am & 0x10u) insert(d4,  p1 + 0);
                if (am & 0x20u) insert(d5,  p1 + 1);
                if (am & 0x40u) insert(d6,  p1 + 2);
                if (am & 0x80u) insert(d7,  p1 + 3);

                const unsigned tu = (unsigned)(thresh >> 32);
                const unsigned ob = (tu & 0x80000000u) ? (tu ^ 0x80000000u) : ~tu;
                thresh_f = __uint_as_float(ob);
            }
        }
    }

    // Pair-merge: warps (2i, 2i+1) hold sorted top-32 of disjoint halves.
    if (active) smerge[wid * 32 + lane] = key;
    __syncthreads();

    if (active && (parity == 0)) {
        // min(A[r], B[31-r]) = lowest-32 of the union (bitonic); then sort.
        unsigned long long mk = ull_min(key, smerge[(wid + 1) * 32 + (31 - lane)]);
        #pragma unroll
        for (int d = 16; d >= 1; d >>= 1) {
            const unsigned long long o = __shfl_xor_sync(FULL, mk, d);
            mk = (lane & d) ? ull_max(mk, o) : ull_min(mk, o);
        }

        const int idx = (int)(mk & 0xffffffffu);
        const float px = sx[idx];
        const float py = sy[idx];
        const float pz = sz[idx];
        const int bg = b * Gg + g;

        float* o0 = out;                                   // neigh [B,G,32,3]
        float* o1 = o0 + (size_t)Bb * Gg * Kk * 3;         // center [B,G,3]
        float* o2 = o1 + (size_t)Bb * Gg * 3;              // labels [B,G,32,1]
        float* o3 = o2 + (size_t)Bb * Gg * Kk;             // idx    [B,G,32]
        float* o4 = o3 + (size_t)Bb * Gg * Kk;             // inside [B,G,32,1]

        const int r0 = (bg * Kk + lane) * 3;
        o0[r0 + 0] = __fsub_rn(px, cx);
        o0[r0 + 1] = __fsub_rn(py, cy);
        o0[r0 + 2] = __fsub_rn(pz, cz);
        if (lane == 0) {
            o1[bg * 3 + 0] = cx;
            o1[bg * 3 + 1] = cy;
            o1[bg * 3 + 2] = cz;
        }
        o2[bg * Kk + lane] = labels[b * Nn + idx];
        o3[bg * Kk + lane] = (float)idx;
        o4[bg * Kk + lane] = inside[b * Nn + idx];
    }
}

extern "C" void kernel_launch(void* const* d_in, const int* in_sizes, int n_in,
                              void* d_out, int out_size) {
    const float* xyz    = (const float*)d_in[0];
    const float* labels = (const float*)d_in[1];
    const float* inside = (const float*)d_in[2];
    float* out = (float*)d_out;

    (void)in_sizes; (void)n_in; (void)out_size;

    init_centers_kernel<<<1, 736>>>();

    const int smem = Nn * 3 * sizeof(float) + 32 * 32 * sizeof(unsigned long long);
    cudaFuncSetAttribute(knn_group_kernel,
                         cudaFuncAttributeMaxDynamicSharedMemorySize, smem);
    dim3 grid((Gg + 15) / 16, Bb);
    knn_group_kernel<<<grid, 1024, smem>>>(xyz, labels, inside, out);
}

// round 7
// speedup vs baseline: 1.1470x; 1.0308x over previous
#include <cuda_runtime.h>
#include <stdint.h>

#define FULL 0xffffffffu

constexpr int Bb = 8;
constexpr int Nn = 16384;
constexpr int Gg = 257;
constexpr int Kk = 32;

// Sphere-grid centers (filled by init kernel each launch; deterministic).
__device__ float g_cx[Gg];
__device__ float g_cy[Gg];
__device__ float g_cz[Gg];

__global__ void init_centers_kernel() {
    __shared__ int pf[736];
    int t = threadIdx.x;            // 736 threads
    int keep = 0;
    float x = 0.f, y = 0.f, z = 0.f;
    if (t < 729) {
        int i = t / 81, j = (t / 9) % 9, k = t % 9;
        x = 0.25f * (float)i - 1.0f;
        y = 0.25f * (float)j - 1.0f;
        z = 0.25f * (float)k - 1.0f;
        float n2 = x * x + y * y + z * z;
        keep = (n2 <= 1.00001f) ? 1 : 0;
    }
    pf[t] = keep;
    __syncthreads();
    for (int s = 1; s < 736; s <<= 1) {
        int v = (t >= s) ? pf[t - s] : 0;
        __syncthreads();
        pf[t] += v;
        __syncthreads();
    }
    if (keep) {
        int p = pf[t] - 1;
        g_cx[p] = x; g_cy[p] = y; g_cz[p] = z;
    }
}

// ---- packed f32x2 exact helpers (two independent IEEE-rn fp32 lanes) ----
__device__ __forceinline__ uint64_t f2fma(uint64_t a, uint64_t b, uint64_t c) {
    uint64_t d; asm("fma.rn.f32x2 %0, %1, %2, %3;" : "=l"(d) : "l"(a), "l"(b), "l"(c));
    return d;
}
__device__ __forceinline__ uint64_t f2mul(uint64_t a, uint64_t b) {
    uint64_t d; asm("mul.rn.f32x2 %0, %1, %2;" : "=l"(d) : "l"(a), "l"(b));
    return d;
}
__device__ __forceinline__ uint64_t f2add(uint64_t a, uint64_t b) {
    uint64_t d; asm("add.rn.f32x2 %0, %1, %2;" : "=l"(d) : "l"(a), "l"(b));
    return d;
}
__device__ __forceinline__ uint64_t f2pack(float lo, float hi) {
    uint64_t d; asm("mov.b64 %0, {%1, %2};" : "=l"(d) : "f"(lo), "f"(hi));
    return d;
}
__device__ __forceinline__ void f2unpack(uint64_t v, float& lo, float& hi) {
    asm("mov.b64 {%0, %1}, %2;" : "=f"(lo), "=f"(hi) : "l"(v));
}

__device__ __forceinline__ unsigned long long ull_min(unsigned long long a,
                                                      unsigned long long b) {
    return a < b ? a : b;
}
__device__ __forceinline__ unsigned long long ull_max(unsigned long long a,
                                                      unsigned long long b) {
    return a < b ? b : a;
}

// 1024 threads: 2 warps per center, each scans half the cloud.
// Prefill: bitonic-sort first 32 points -> real threshold from the start.
__global__ __launch_bounds__(1024, 1)
void knn_group_kernel(const float* __restrict__ xyz,
                      const float* __restrict__ labels,
                      const float* __restrict__ inside,
                      float* __restrict__ out) {
    extern __shared__ float s[];                 // sx|sy|sz (+ merge buf)
    float* sx = s;
    float* sy = s + Nn;
    float* sz = s + 2 * Nn;
    unsigned long long* smerge =
        reinterpret_cast<unsigned long long*>(s + 3 * Nn);   // 32 warps * 32

    const int b = blockIdx.y;
    const int tid = threadIdx.x;

    // AoS global -> SoA shared (float4 coalesced loads, scalar stores).
    {
        const float4* src = reinterpret_cast<const float4*>(xyz + (size_t)b * Nn * 3);
        for (int i = tid; i < Nn * 3 / 4; i += blockDim.x) {
            const float4 v = src[i];
            const int e = 4 * i;
            s[(e % 3) * Nn + e / 3]             = v.x;
            s[((e + 1) % 3) * Nn + (e + 1) / 3] = v.y;
            s[((e + 2) % 3) * Nn + (e + 2) / 3] = v.z;
            s[((e + 3) % 3) * Nn + (e + 3) / 3] = v.w;
        }
    }
    __syncthreads();

    const int wid    = tid >> 5;      // 0..31
    const int lane   = tid & 31;
    const int gi     = wid >> 1;      // center slot 0..15
    const int parity = wid & 1;       // which half of the cloud
    const int g      = blockIdx.x * 16 + gi;
    const bool active = (g < Gg);

    unsigned long long key = ~0ull;   // lane r = rank-r key, ascending
    float cx = 0.f, cy = 0.f, cz = 0.f;

    if (active) {
        cx = g_cx[g]; cy = g_cy[g]; cz = g_cz[g];
        const float c2 = cx * cx + cy * cy + cz * cz;   // exact lattice arith

        const uint64_t cx2 = f2pack(cx, cx);
        const uint64_t cy2 = f2pack(cy, cy);
        const uint64_t cz2 = f2pack(cz, cz);
        const uint64_t c22 = f2pack(c2, c2);
        const uint64_t n22 = f2pack(-2.0f, -2.0f);

        // FROZEN scalar precision model (verified rel_err == 0):
        //   x2 = fma(z,z, fma(y,y, rn(x*x)))
        //   dt = fma(cz,z, fma(cy,y, rn(cx*x)))
        //   d2 = (c2 + x2) - rn(2*dt)
        auto d2exact = [&](float x, float y, float z) -> float {
            const float x2 = __fmaf_rn(z, z, __fmaf_rn(y, y, __fmul_rn(x, x)));
            const float dt = __fmaf_rn(cz, z, __fmaf_rn(cy, y, __fmul_rn(cx, x)));
            return __fsub_rn(__fadd_rn(c2, x2), __fmul_rn(2.0f, dt));
        };
        auto mkkey = [](float d2v, int p) -> unsigned long long {
            unsigned uu = __float_as_uint(d2v);
            uu = (uu & 0x80000000u) ? ~uu : (uu | 0x80000000u);
            return ((unsigned long long)uu << 32) | (unsigned)p;
        };

        const int half_pt = parity * (Nn / 2);      // 0 or 8192 (points)
        const int half4   = parity * (Nn / 8);      // float4 units

        // ---- Prefill: bitonic sort-32 of the first 32 points of the half ----
        {
            const int p = half_pt + lane;
            key = mkkey(d2exact(sx[p], sy[p], sz[p]), p);
            #pragma unroll
            for (int k = 2; k <= 32; k <<= 1) {
                #pragma unroll
                for (int j = k >> 1; j >= 1; j >>= 1) {
                    const unsigned long long o = __shfl_xor_sync(FULL, key, j);
                    const bool dir = ((lane & k) == 0);
                    const bool keep_min = (((lane & j) == 0) == dir);
                    key = keep_min ? ull_min(key, o) : ull_max(key, o);
                }
            }
        }
        unsigned long long thresh = __shfl_sync(FULL, key, 31);
        {
            const unsigned tu = (unsigned)(thresh >> 32);
            const unsigned ob = (tu & 0x80000000u) ? (tu ^ 0x80000000u) : ~tu;
            // fallthrough below
            // (thresh_f declared after to keep live range tight)
            // nothing
            (void)ob;
        }
        float thresh_f;
        {
            const unsigned tu = (unsigned)(thresh >> 32);
            const unsigned ob = (tu & 0x80000000u) ? (tu ^ 0x80000000u) : ~tu;
            thresh_f = __uint_as_float(ob);
        }

        // Exact 64-bit key insertion into the sorted-per-lane top-32.
        auto insert = [&](float d2v, int p) {
            const unsigned long long nk = mkkey(d2v, p);
            unsigned m = __ballot_sync(FULL, nk < thresh);
            while (m) {
                const int srcl = __ffs(m) - 1;
                m &= m - 1;
                const unsigned long long cand = __shfl_sync(FULL, nk, srcl);
                if (cand >= thresh) continue;
                const int pos = __popc(__ballot_sync(FULL, key < cand));
                const unsigned long long up = __shfl_up_sync(FULL, key, 1);
                if (lane > pos)       key = up;
                else if (lane == pos) key = cand;
                thresh = __shfl_sync(FULL, key, 31);
            }
        };
        auto refresh = [&]() {
            const unsigned tu = (unsigned)(thresh >> 32);
            const unsigned ob = (tu & 0x80000000u) ? (tu ^ 0x80000000u) : ~tu;
            thresh_f = __uint_as_float(ob);
        };

        // ---- Mini-rounds: points 32..255 of the half (7 x 32, scalar) ----
        #pragma unroll
        for (int i = 0; i < 7; ++i) {
            const int p = half_pt + 32 + i * 32 + lane;
            const float d2v = d2exact(sx[p], sy[p], sz[p]);
            if (__ballot_sync(FULL, d2v <= thresh_f)) {
                insert(d2v, p);
                refresh();
            }
        }

        // ---- Full rounds: points 256..8191 of the half (31 x 256) ----
        auto d2pair = [&](uint64_t xp, uint64_t yp, uint64_t zp) -> uint64_t {
            const uint64_t x2 = f2fma(zp, zp, f2fma(yp, yp, f2mul(xp, xp)));
            const uint64_t dt = f2fma(cz2, zp, f2fma(cy2, yp, f2mul(cx2, xp)));
            return f2add(f2add(c22, x2), f2mul(dt, n22));
        };

        for (int it = 1; it < 32; ++it) {
            const int j0 = half4 + it * 64 + lane;
            const int j1 = j0 + 32;

            const ulonglong2 xa = *reinterpret_cast<const ulonglong2*>(sx + 4 * j0);
            const ulonglong2 ya = *reinterpret_cast<const ulonglong2*>(sy + 4 * j0);
            const ulonglong2 za = *reinterpret_cast<const ulonglong2*>(sz + 4 * j0);
            const ulonglong2 xb = *reinterpret_cast<const ulonglong2*>(sx + 4 * j1);
            const ulonglong2 yb = *reinterpret_cast<const ulonglong2*>(sy + 4 * j1);
            const ulonglong2 zb = *reinterpret_cast<const ulonglong2*>(sz + 4 * j1);

            const uint64_t dA = d2pair(xa.x, ya.x, za.x);   // pts 4j0+0,1
            const uint64_t dB = d2pair(xa.y, ya.y, za.y);   // pts 4j0+2,3
            const uint64_t dC = d2pair(xb.x, yb.x, zb.x);   // pts 4j1+0,1
            const uint64_t dD = d2pair(xb.y, yb.y, zb.y);   // pts 4j1+2,3

            float d0, d1, d2_, d3, d4, d5, d6, d7;
            f2unpack(dA, d0, d1);
            f2unpack(dB, d2_, d3);
            f2unpack(dC, d4, d5);
            f2unpack(dD, d6, d7);

            const float m01 = fminf(d0, d1), m23 = fminf(d2_, d3);
            const float m45 = fminf(d4, d5), m67 = fminf(d6, d7);
            const float min8 = fminf(fminf(m01, m23), fminf(m45, m67));

            if (__ballot_sync(FULL, min8 <= thresh_f)) {
                unsigned bits = 0;
                bits |= (d0  <= thresh_f) ? 0x01u : 0u;
                bits |= (d1  <= thresh_f) ? 0x02u : 0u;
                bits |= (d2_ <= thresh_f) ? 0x04u : 0u;
                bits |= (d3  <= thresh_f) ? 0x08u : 0u;
                bits |= (d4  <= thresh_f) ? 0x10u : 0u;
                bits |= (d5  <= thresh_f) ? 0x20u : 0u;
                bits |= (d6  <= thresh_f) ? 0x40u : 0u;
                bits |= (d7  <= thresh_f) ? 0x80u : 0u;
                const unsigned am = __reduce_or_sync(FULL, bits);  // uniform

                const int p0 = 4 * j0, p1 = 4 * j1;
                if (am & 0x01u) insert(d0,  p0 + 0);
                if (am & 0x02u) insert(d1,  p0 + 1);
                if (am & 0x04u) insert(d2_, p0 + 2);
                if (am & 0x08u) insert(d3,  p0 + 3);
                if (am & 0x10u) insert(d4,  p1 + 0);
                if (am & 0x20u) insert(d5,  p1 + 1);
                if (am & 0x40u) insert(d6,  p1 + 2);
                if (am & 0x80u) insert(d7,  p1 + 3);
                refresh();
            }
        }
    }

    // Pair-merge: warps (2i, 2i+1) hold sorted top-32 of disjoint halves.
    if (active) smerge[wid * 32 + lane] = key;
    __syncthreads();

    if (active && (parity == 0)) {
        // min(A[r], B[31-r]) = lowest-32 of the union (bitonic); then sort.
        unsigned long long mk = ull_min(key, smerge[(wid + 1) * 32 + (31 - lane)]);
        #pragma unroll
        for (int d = 16; d >= 1; d >>= 1) {
            const unsigned long long o = __shfl_xor_sync(FULL, mk, d);
            mk = (lane & d) ? ull_max(mk, o) : ull_min(mk, o);
        }

        const int idx = (int)(mk & 0xffffffffu);
        const float px = sx[idx];
        const float py = sy[idx];
        const float pz = sz[idx];
        const int bg = b * Gg + g;

        float* o0 = out;                                   // neigh [B,G,32,3]
        float* o1 = o0 + (size_t)Bb * Gg * Kk * 3;         // center [B,G,3]
        float* o2 = o1 + (size_t)Bb * Gg * 3;              // labels [B,G,32,1]
        float* o3 = o2 + (size_t)Bb * Gg * Kk;             // idx    [B,G,32]
        float* o4 = o3 + (size_t)Bb * Gg * Kk;             // inside [B,G,32,1]

        const int r0 = (bg * Kk + lane) * 3;
        o0[r0 + 0] = __fsub_rn(px, cx);
        o0[r0 + 1] = __fsub_rn(py, cy);
        o0[r0 + 2] = __fsub_rn(pz, cz);
        if (lane == 0) {
            o1[bg * 3 + 0] = cx;
            o1[bg * 3 + 1] = cy;
            o1[bg * 3 + 2] = cz;
        }
        o2[bg * Kk + lane] = labels[b * Nn + idx];
        o3[bg * Kk + lane] = (float)idx;
        o4[bg * Kk + lane] = inside[b * Nn + idx];
    }
}

extern "C" void kernel_launch(void* const* d_in, const int* in_sizes, int n_in,
                              void* d_out, int out_size) {
    const float* xyz    = (const float*)d_in[0];
    const float* labels = (const float*)d_in[1];
    const float* inside = (const float*)d_in[2];
    float* out = (float*)d_out;

    (void)in_sizes; (void)n_in; (void)out_size;

    init_centers_kernel<<<1, 736>>>();

    const int smem = Nn * 3 * sizeof(float) + 32 * 32 * sizeof(unsigned long long);
    cudaFuncSetAttribute(knn_group_kernel,
                         cudaFuncAttributeMaxDynamicSharedMemorySize, smem);
    dim3 grid((Gg + 15) / 16, Bb);
    knn_group_kernel<<<grid, 1024, smem>>>(xyz, labels, inside, out);
}

// round 8
// speedup vs baseline: 1.3324x; 1.1617x over previous
#include <cuda_runtime.h>
#include <stdint.h>

#define FULL 0xffffffffu

constexpr int Bb = 8;
constexpr int Nn = 16384;
constexpr int Gg = 257;
constexpr int Kk = 32;

// Sphere-grid centers (filled by init kernel each launch; deterministic).
__device__ float g_cx[Gg];
__device__ float g_cy[Gg];
__device__ float g_cz[Gg];

__global__ void init_centers_kernel() {
    __shared__ int pf[736];
    int t = threadIdx.x;            // 736 threads
    int keep = 0;
    float x = 0.f, y = 0.f, z = 0.f;
    if (t < 729) {
        int i = t / 81, j = (t / 9) % 9, k = t % 9;
        x = 0.25f * (float)i - 1.0f;
        y = 0.25f * (float)j - 1.0f;
        z = 0.25f * (float)k - 1.0f;
        float n2 = x * x + y * y + z * z;
        keep = (n2 <= 1.00001f) ? 1 : 0;
    }
    pf[t] = keep;
    __syncthreads();
    for (int s = 1; s < 736; s <<= 1) {
        int v = (t >= s) ? pf[t - s] : 0;
        __syncthreads();
        pf[t] += v;
        __syncthreads();
    }
    if (keep) {
        int p = pf[t] - 1;
        g_cx[p] = x; g_cy[p] = y; g_cz[p] = z;
    }
}

// ---- packed f32x2 exact helpers (two independent IEEE-rn fp32 lanes) ----
__device__ __forceinline__ uint64_t f2fma(uint64_t a, uint64_t b, uint64_t c) {
    uint64_t d; asm("fma.rn.f32x2 %0, %1, %2, %3;" : "=l"(d) : "l"(a), "l"(b), "l"(c));
    return d;
}
__device__ __forceinline__ uint64_t f2mul(uint64_t a, uint64_t b) {
    uint64_t d; asm("mul.rn.f32x2 %0, %1, %2;" : "=l"(d) : "l"(a), "l"(b));
    return d;
}
__device__ __forceinline__ uint64_t f2add(uint64_t a, uint64_t b) {
    uint64_t d; asm("add.rn.f32x2 %0, %1, %2;" : "=l"(d) : "l"(a), "l"(b));
    return d;
}
__device__ __forceinline__ uint64_t f2pack(float lo, float hi) {
    uint64_t d; asm("mov.b64 %0, {%1, %2};" : "=l"(d) : "f"(lo), "f"(hi));
    return d;
}
__device__ __forceinline__ void f2unpack(uint64_t v, float& lo, float& hi) {
    asm("mov.b64 {%0, %1}, %2;" : "=f"(lo), "=f"(hi) : "l"(v));
}

__device__ __forceinline__ unsigned long long ull_min(unsigned long long a,
                                                      unsigned long long b) {
    return a < b ? a : b;
}
__device__ __forceinline__ unsigned long long ull_max(unsigned long long a,
                                                      unsigned long long b) {
    return a < b ? b : a;
}

// 1024 threads: 2 warps per center, each scans half the cloud.
// Partner-threshold pruning: warp pairs share their 32nd-best via SMEM, so
// each half only retains candidates that can be in the UNION top-32 (exact).
__global__ __launch_bounds__(1024, 1)
void knn_group_kernel(const float* __restrict__ xyz,
                      const float* __restrict__ labels,
                      const float* __restrict__ inside,
                      float* __restrict__ out) {
    extern __shared__ float s[];                 // sx|sy|sz | merge | vth
    float* sx = s;
    float* sy = s + Nn;
    float* sz = s + 2 * Nn;
    unsigned long long* smerge =
        reinterpret_cast<unsigned long long*>(s + 3 * Nn);   // 32 warps * 32
    volatile float* vth =
        reinterpret_cast<volatile float*>(s + 3 * Nn + 2 * 32 * 32); // 32 floats

    const int b = blockIdx.y;
    const int tid = threadIdx.x;

    // AoS global -> SoA shared (float4 coalesced loads, scalar stores).
    {
        const float4* src = reinterpret_cast<const float4*>(xyz + (size_t)b * Nn * 3);
        for (int i = tid; i < Nn * 3 / 4; i += blockDim.x) {
            const float4 v = src[i];
            const int e = 4 * i;
            s[(e % 3) * Nn + e / 3]             = v.x;
            s[((e + 1) % 3) * Nn + (e + 1) / 3] = v.y;
            s[((e + 2) % 3) * Nn + (e + 2) / 3] = v.z;
            s[((e + 3) % 3) * Nn + (e + 3) / 3] = v.w;
        }
        if (tid < 32) vth[tid] = __int_as_float(0x7f800000);   // +inf
    }
    __syncthreads();

    const int wid    = tid >> 5;      // 0..31
    const int lane   = tid & 31;
    const int gi     = wid >> 1;      // center slot 0..15
    const int parity = wid & 1;       // which half of the cloud
    const int g      = blockIdx.x * 16 + gi;
    const bool active = (g < Gg);

    unsigned long long key = ~0ull;   // lane r = rank-r key, ascending
    float cx = 0.f, cy = 0.f, cz = 0.f;

    if (active) {
        cx = g_cx[g]; cy = g_cy[g]; cz = g_cz[g];
        const float c2 = cx * cx + cy * cy + cz * cz;   // exact lattice arith

        const uint64_t cx2 = f2pack(cx, cx);
        const uint64_t cy2 = f2pack(cy, cy);
        const uint64_t cz2 = f2pack(cz, cz);
        const uint64_t c22 = f2pack(c2, c2);
        const uint64_t n22 = f2pack(-2.0f, -2.0f);

        // FROZEN scalar precision model (verified rel_err == 0):
        //   x2 = fma(z,z, fma(y,y, rn(x*x)))
        //   dt = fma(cz,z, fma(cy,y, rn(cx*x)))
        //   d2 = (c2 + x2) - rn(2*dt)
        auto d2exact = [&](float x, float y, float z) -> float {
            const float x2 = __fmaf_rn(z, z, __fmaf_rn(y, y, __fmul_rn(x, x)));
            const float dt = __fmaf_rn(cz, z, __fmaf_rn(cy, y, __fmul_rn(cx, x)));
            return __fsub_rn(__fadd_rn(c2, x2), __fmul_rn(2.0f, dt));
        };
        auto mkkey = [](float d2v, int p) -> unsigned long long {
            unsigned uu = __float_as_uint(d2v);
            uu = (uu & 0x80000000u) ? ~uu : (uu | 0x80000000u);
            return ((unsigned long long)uu << 32) | (unsigned)p;
        };

        const int half_pt = parity * (Nn / 2);      // 0 or 8192 (points)
        const int half4   = parity * (Nn / 8);      // float4 units
        const int pw      = wid ^ 1;                // partner warp

        // ---- Prefill: bitonic sort-32 of the first 32 points of the half ----
        {
            const int p = half_pt + lane;
            key = mkkey(d2exact(sx[p], sy[p], sz[p]), p);
            #pragma unroll
            for (int k = 2; k <= 32; k <<= 1) {
                #pragma unroll
                for (int j = k >> 1; j >= 1; j >>= 1) {
                    const unsigned long long o = __shfl_xor_sync(FULL, key, j);
                    const bool dir = ((lane & k) == 0);
                    const bool keep_min = (((lane & j) == 0) == dir);
                    key = keep_min ? ull_min(key, o) : ull_max(key, o);
                }
            }
        }
        unsigned long long thresh = __shfl_sync(FULL, key, 31);
        float thresh_f;
        {
            const unsigned tu = (unsigned)(thresh >> 32);
            const unsigned ob = (tu & 0x80000000u) ? (tu ^ 0x80000000u) : ~tu;
            thresh_f = __uint_as_float(ob);
        }
        if (lane == 0) vth[wid] = thresh_f;

        // Slim insert: no per-iteration staleness check or thresh reshuffle —
        // stale candidates no-op automatically (pos==32 matches no lane).
        auto insert = [&](float d2v, int p) {
            const unsigned long long nk = mkkey(d2v, p);
            unsigned m = __ballot_sync(FULL, nk < thresh);
            while (m) {
                const int srcl = __ffs(m) - 1;
                m &= m - 1;
                const unsigned long long cand = __shfl_sync(FULL, nk, srcl);
                const int pos = __popc(__ballot_sync(FULL, key < cand));
                const unsigned long long up = __shfl_up_sync(FULL, key, 1);
                if (lane > pos)       key = up;
                else if (lane == pos) key = cand;
            }
        };
        auto round_refresh = [&]() {
            thresh = __shfl_sync(FULL, key, 31);
            const unsigned tu = (unsigned)(thresh >> 32);
            const unsigned ob = (tu & 0x80000000u) ? (tu ^ 0x80000000u) : ~tu;
            thresh_f = __uint_as_float(ob);
            if (lane == 0) vth[wid] = thresh_f;
        };

        // ---- Mini-rounds: points 32..255 of the half (7 x 32, scalar) ----
        #pragma unroll
        for (int i = 0; i < 7; ++i) {
            const int p = half_pt + 32 + i * 32 + lane;
            const float d2v = d2exact(sx[p], sy[p], sz[p]);
            const float tg = fminf(thresh_f, vth[pw]);   // partner prune
            if (__ballot_sync(FULL, d2v <= tg)) {
                insert(d2v, p);
                round_refresh();
            }
        }

        // ---- Full rounds: points 256..8191 of the half (31 x 256) ----
        auto d2pair = [&](uint64_t xp, uint64_t yp, uint64_t zp) -> uint64_t {
            const uint64_t x2 = f2fma(zp, zp, f2fma(yp, yp, f2mul(xp, xp)));
            const uint64_t dt = f2fma(cz2, zp, f2fma(cy2, yp, f2mul(cx2, xp)));
            return f2add(f2add(c22, x2), f2mul(dt, n22));
        };

        for (int it = 1; it < 32; ++it) {
            const int j0 = half4 + it * 64 + lane;
            const int j1 = j0 + 32;

            const ulonglong2 xa = *reinterpret_cast<const ulonglong2*>(sx + 4 * j0);
            const ulonglong2 ya = *reinterpret_cast<const ulonglong2*>(sy + 4 * j0);
            const ulonglong2 za = *reinterpret_cast<const ulonglong2*>(sz + 4 * j0);
            const ulonglong2 xb = *reinterpret_cast<const ulonglong2*>(sx + 4 * j1);
            const ulonglong2 yb = *reinterpret_cast<const ulonglong2*>(sy + 4 * j1);
            const ulonglong2 zb = *reinterpret_cast<const ulonglong2*>(sz + 4 * j1);

            const uint64_t dA = d2pair(xa.x, ya.x, za.x);   // pts 4j0+0,1
            const uint64_t dB = d2pair(xa.y, ya.y, za.y);   // pts 4j0+2,3
            const uint64_t dC = d2pair(xb.x, yb.x, zb.x);   // pts 4j1+0,1
            const uint64_t dD = d2pair(xb.y, yb.y, zb.y);   // pts 4j1+2,3

            float d0, d1, d2_, d3, d4, d5, d6, d7;
            f2unpack(dA, d0, d1);
            f2unpack(dB, d2_, d3);
            f2unpack(dC, d4, d5);
            f2unpack(dD, d6, d7);

            const float m01 = fminf(d0, d1), m23 = fminf(d2_, d3);
            const float m45 = fminf(d4, d5), m67 = fminf(d6, d7);
            const float min8 = fminf(fminf(m01, m23), fminf(m45, m67));

            const float tg = fminf(thresh_f, vth[pw]);   // partner prune

            if (__ballot_sync(FULL, min8 <= tg)) {
                unsigned bits = 0;
                bits |= (d0  <= tg) ? 0x01u : 0u;
                bits |= (d1  <= tg) ? 0x02u : 0u;
                bits |= (d2_ <= tg) ? 0x04u : 0u;
                bits |= (d3  <= tg) ? 0x08u : 0u;
                bits |= (d4  <= tg) ? 0x10u : 0u;
                bits |= (d5  <= tg) ? 0x20u : 0u;
                bits |= (d6  <= tg) ? 0x40u : 0u;
                bits |= (d7  <= tg) ? 0x80u : 0u;
                const unsigned am = __reduce_or_sync(FULL, bits);  // uniform

                const int p0 = 4 * j0, p1 = 4 * j1;
                if (am & 0x01u) insert(d0,  p0 + 0);
                if (am & 0x02u) insert(d1,  p0 + 1);
                if (am & 0x04u) insert(d2_, p0 + 2);
                if (am & 0x08u) insert(d3,  p0 + 3);
                if (am & 0x10u) insert(d4,  p1 + 0);
                if (am & 0x20u) insert(d5,  p1 + 1);
                if (am & 0x40u) insert(d6,  p1 + 2);
                if (am & 0x80u) insert(d7,  p1 + 3);
                round_refresh();
            }
        }
    }

    // Pair-merge: warps (2i, 2i+1) hold (pruned) top-32 lists whose union
    // provably contains the exact union top-32.
    if (active) smerge[wid * 32 + lane] = key;
    __syncthreads();

    if (active && (parity == 0)) {
        // min(A[r], B[31-r]) = lowest-32 of the union (bitonic); then sort.
        unsigned long long mk = ull_min(key, smerge[(wid + 1) * 32 + (31 - lane)]);
        #pragma unroll
        for (int d = 16; d >= 1; d >>= 1) {
            const unsigned long long o = __shfl_xor_sync(FULL, mk, d);
            mk = (lane & d) ? ull_max(mk, o) : ull_min(mk, o);
        }

        const int idx = (int)(mk & 0xffffffffu);
        const float px = sx[idx];
        const float py = sy[idx];
        const float pz = sz[idx];
        const int bg = b * Gg + g;

        float* o0 = out;                                   // neigh [B,G,32,3]
        float* o1 = o0 + (size_t)Bb * Gg * Kk * 3;         // center [B,G,3]
        float* o2 = o1 + (size_t)Bb * Gg * 3;              // labels [B,G,32,1]
        float* o3 = o2 + (size_t)Bb * Gg * Kk;             // idx    [B,G,32]
        float* o4 = o3 + (size_t)Bb * Gg * Kk;             // inside [B,G,32,1]

        const int r0 = (bg * Kk + lane) * 3;
        o0[r0 + 0] = __fsub_rn(px, cx);
        o0[r0 + 1] = __fsub_rn(py, cy);
        o0[r0 + 2] = __fsub_rn(pz, cz);
        if (lane == 0) {
            o1[bg * 3 + 0] = cx;
            o1[bg * 3 + 1] = cy;
            o1[bg * 3 + 2] = cz;
        }
        o2[bg * Kk + lane] = labels[b * Nn + idx];
        o3[bg * Kk + lane] = (float)idx;
        o4[bg * Kk + lane] = inside[b * Nn + idx];
    }
}

extern "C" void kernel_launch(void* const* d_in, const int* in_sizes, int n_in,
                              void* d_out, int out_size) {
    const float* xyz    = (const float*)d_in[0];
    const float* labels = (const float*)d_in[1];
    const float* inside = (const float*)d_in[2];
    float* out = (float*)d_out;

    (void)in_sizes; (void)n_in; (void)out_size;

    init_centers_kernel<<<1, 736>>>();

    const int smem = Nn * 3 * sizeof(float)
                   + 32 * 32 * sizeof(unsigned long long)
                   + 32 * sizeof(float);
    cudaFuncSetAttribute(knn_group_kernel,
                         cudaFuncAttributeMaxDynamicSharedMemorySize, smem);
    dim3 grid((Gg + 15) / 16, Bb);
    knn_group_kernel<<<grid, 1024, smem>>>(xyz, labels, inside, out);
}